// round 10
// baseline (speedup 1.0000x reference)
#include <cuda_runtime.h>
#include <cstdint>

// Problem constants (fixed by the reference: B=16, L=4096, D=512, WORD_SIZE=128, WORD_LEN=2)
#define NWORDS 32768     // B * (L/2)
#define DIM    512
#define NC     128       // codebook rows
#define BM     128       // words per CTA tile
#define BK     16        // k-chunk
#define BMP    (BM + 4)  // A smem pitch
#define NCP2   144       // B smem pitch (gap-padded layout, see bcol_of)
#define NCHUNK (DIM / BK)
#define GRID   (NWORDS / BM)   // 256 CTAs

// Scratch (no allocations allowed -> __device__ globals)
__device__ float    g_s_part[GRID][NC];  // per-CTA partial ||P-C||^2 (2 d-cols each)
__device__ int      g_count[NC];         // histogram of argmin indices
__device__ unsigned g_done;              // last-CTA election (zero-init; reset by last CTA)

// B smem column mapping: 4-float gap every 32 codes -> the 8 per-warp LDS.128
// addresses land in distinct bank quads (conflict-free).
__device__ __forceinline__ int bcol_of(int c) { return c + ((c >> 5) << 2); }

// ---- packed f32x2 helpers (each half = independent IEEE fp32 op) -----------
__device__ __forceinline__ unsigned long long dup2(float x) {
    unsigned long long r;
    asm("mov.b64 %0, {%1, %1};" : "=l"(r) : "f"(x));
    return r;
}
__device__ __forceinline__ void ffma2(unsigned long long& d,
                                      unsigned long long a,
                                      unsigned long long b) {
    asm("fma.rn.f32x2 %0, %1, %2, %0;" : "+l"(d) : "l"(a), "l"(b));
}
__device__ __forceinline__ float2 unpack2(unsigned long long v) {
    float2 f;
    asm("mov.b64 {%0, %1}, %2;" : "=f"(f.x), "=f"(f.y) : "l"(v));
    return f;
}

// Overlay: GEMM tile buffers (main loop) vs epilogue arrays (after loop).
struct MainBufs {
    float m[2][BK][BMP];    // 16.9 KB
    float c[2][BK][NCP2];   // 18.4 KB
};
struct EpiBufs {
    float fold[BM][17];     // mnorm chains; cols 0..3 reused for cnorm
    float bs[BM][17];       // per-(word, co-group) best score
    int   bi[BM][17];       // and best index
};

// ---------------------------------------------------------------------------
// Single fused kernel:
//   prep-slice (2 d-cols of ||C@W^T+b-C||^2) -> pair-sum + mnorm(LLVM order)
//   + cnorm -> fp32 GEMM (f32x2, double-buffered, conflict-free B smem)
//   -> d2 rounding chain -> smem argmin -> histogram -> gather -> last-CTA loss.
//
// Bit-exactness invariants (rel_err==0.0 verified R7/R8, preserved):
//  * per-(word,code) dot: single fp32 accumulator, FMA over ascending k.
//  * mnorm: 16 chains part_p[l] = sum_i y[16i+4p+l] (ascending chunk i;
//    loader lq == p, component == l), fold ((P0+P1)+P2)+P3, (v0+v1)+(v2+v3).
//  * d2 = fl(fl(mnorm - acc) + cnorm); argmin first-min (lowest index).
//  * cnorm/loss: fixed fold order (loss-only precision, slack is huge).
// ---------------------------------------------------------------------------
__global__ __launch_bounds__(256, 2)
void main_kernel(const float* __restrict__ emb,   // [NWORDS*2, DIM]
                 const float* __restrict__ cb,    // [NC, DIM]
                 const float* __restrict__ W,     // [DIM, DIM]
                 const float* __restrict__ bias,  // [DIM]
                 float* __restrict__ out_idx,     // NWORDS floats
                 float* __restrict__ out_emb,     // NWORDS*DIM floats
                 float* __restrict__ out_loss) {  // 1 float
    __shared__ __align__(16) union { MainBufs mb; EpiBufs eb; } u;   // 35.3 KB
    __shared__ float sm_mn[BM];
    __shared__ float sm_cn[NC];
    __shared__ float sm_ls[8];
    __shared__ int   widx[BM];
    __shared__ int   hist[NC];
    __shared__ int   is_last;

    const int t = threadIdx.x;
    const int bid = blockIdx.x;
    const int wbase = bid * BM;

    if (t < NC) hist[t] = 0;

    // compute-map: warp tile = 32 words x 64 codes (4 wq x 8 cq)
    const int w  = t >> 5, l = t & 31;
    const int wo = ((w >> 1) << 2) + (l >> 3);   // 0..15 word group (8 words)
    const int co = ((w & 1) << 3) + (l & 7);     // 0..15 code group (8 codes)
    // loader-map (fixed: mnorm chain identity depends on it)
    const int lw = t >> 2;   // 0..63
    const int lq = t & 3;    // 0..3  (== mnorm part index p)

    unsigned long long acc2[8][4];
    #pragma unroll
    for (int i = 0; i < 8; i++)
        #pragma unroll
        for (int jp = 0; jp < 4; jp++) acc2[i][jp] = 0ull;

    float4 macc0 = make_float4(0.f, 0.f, 0.f, 0.f);
    float4 macc1 = make_float4(0.f, 0.f, 0.f, 0.f);
    float  cnacc0 = 0.f, cnacc1 = 0.f;

    float4 pa00, pa01, pa10, pa11, pb0, pb1;

    auto do_ldg = [&](int c) {
        const int kc = c * BK;
        const size_t r0 = (size_t)(wbase + lw) * 2 * DIM + kc + lq * 4;
        const size_t r1 = r0 + (size_t)64 * 2 * DIM;
        pa00 = *(const float4*)(emb + r0);
        pa01 = *(const float4*)(emb + r0 + DIM);
        pa10 = *(const float4*)(emb + r1);
        pa11 = *(const float4*)(emb + r1 + DIM);
        pb0  = *(const float4*)(cb + (size_t)lw * DIM + kc + lq * 4);
        pb1  = *(const float4*)(cb + (size_t)(64 + lw) * DIM + kc + lq * 4);
    };

    const int bc0 = bcol_of(lw);        // B smem column for code lw
    const int bc1 = bcol_of(64 + lw);   // and code 64+lw

    auto do_store = [&](int buf) {
        float (*mm)[BMP]  = u.mb.m[buf];
        float (*cc)[NCP2] = u.mb.c[buf];
        float s0 = __fadd_rn(pa00.x, pa01.x);
        float s1 = __fadd_rn(pa00.y, pa01.y);
        float s2 = __fadd_rn(pa00.z, pa01.z);
        float s3 = __fadd_rn(pa00.w, pa01.w);
        mm[lq * 4 + 0][lw] = s0;
        mm[lq * 4 + 1][lw] = s1;
        mm[lq * 4 + 2][lw] = s2;
        mm[lq * 4 + 3][lw] = s3;
        float m0 = __fmul_rn(s0, 0.5f), m1 = __fmul_rn(s1, 0.5f);
        float m2 = __fmul_rn(s2, 0.5f), m3 = __fmul_rn(s3, 0.5f);
        macc0.x = __fadd_rn(macc0.x, __fmul_rn(m0, m0));
        macc0.y = __fadd_rn(macc0.y, __fmul_rn(m1, m1));
        macc0.z = __fadd_rn(macc0.z, __fmul_rn(m2, m2));
        macc0.w = __fadd_rn(macc0.w, __fmul_rn(m3, m3));

        s0 = __fadd_rn(pa10.x, pa11.x);
        s1 = __fadd_rn(pa10.y, pa11.y);
        s2 = __fadd_rn(pa10.z, pa11.z);
        s3 = __fadd_rn(pa10.w, pa11.w);
        mm[lq * 4 + 0][64 + lw] = s0;
        mm[lq * 4 + 1][64 + lw] = s1;
        mm[lq * 4 + 2][64 + lw] = s2;
        mm[lq * 4 + 3][64 + lw] = s3;
        m0 = __fmul_rn(s0, 0.5f); m1 = __fmul_rn(s1, 0.5f);
        m2 = __fmul_rn(s2, 0.5f); m3 = __fmul_rn(s3, 0.5f);
        macc1.x = __fadd_rn(macc1.x, __fmul_rn(m0, m0));
        macc1.y = __fadd_rn(macc1.y, __fmul_rn(m1, m1));
        macc1.z = __fadd_rn(macc1.z, __fmul_rn(m2, m2));
        macc1.w = __fadd_rn(macc1.w, __fmul_rn(m3, m3));

        cc[lq * 4 + 0][bc0] = pb0.x;
        cc[lq * 4 + 1][bc0] = pb0.y;
        cc[lq * 4 + 2][bc0] = pb0.z;
        cc[lq * 4 + 3][bc0] = pb0.w;
        cc[lq * 4 + 0][bc1] = pb1.x;
        cc[lq * 4 + 1][bc1] = pb1.y;
        cc[lq * 4 + 2][bc1] = pb1.z;
        cc[lq * 4 + 3][bc1] = pb1.w;
        cnacc0 = __fmaf_rn(pb0.x, pb0.x, cnacc0);
        cnacc0 = __fmaf_rn(pb0.y, pb0.y, cnacc0);
        cnacc0 = __fmaf_rn(pb0.z, pb0.z, cnacc0);
        cnacc0 = __fmaf_rn(pb0.w, pb0.w, cnacc0);
        cnacc1 = __fmaf_rn(pb1.x, pb1.x, cnacc1);
        cnacc1 = __fmaf_rn(pb1.y, pb1.y, cnacc1);
        cnacc1 = __fmaf_rn(pb1.z, pb1.z, cnacc1);
        cnacc1 = __fmaf_rn(pb1.w, pb1.w, cnacc1);
    };

    // ---- issue chunk-0 loads, then overlap the prep slice under their latency
    do_ldg(0);

    // prep slice: this CTA owns d-columns {2*bid, 2*bid+1}.
    // thread t: code = t>>1, d = 2*bid + (t&1).  Loss-only -> any dot order.
    {
        const int code = t >> 1;
        const int d    = bid * 2 + (t & 1);
        const float4* c4 = (const float4*)(cb + (size_t)code * DIM);
        const float4* w4 = (const float4*)(W + (size_t)d * DIM);
        float p0 = 0.f, p1 = 0.f, p2 = 0.f, p3 = 0.f;
        #pragma unroll 8
        for (int i = 0; i < DIM / 4; i++) {
            float4 a = __ldg(&c4[i]);
            float4 b = __ldg(&w4[i]);
            p0 = __fmaf_rn(a.x, b.x, p0);
            p1 = __fmaf_rn(a.y, b.y, p1);
            p2 = __fmaf_rn(a.z, b.z, p2);
            p3 = __fmaf_rn(a.w, b.w, p3);
        }
        float p = __fadd_rn(__fadd_rn(p0, p1), __fadd_rn(p2, p3));
        float diff = p + __ldg(&bias[d]) - __ldg(&cb[(size_t)code * DIM + d]);
        float sq = diff * diff;
        float other = __shfl_xor_sync(0xffffffffu, sq, 1);
        if ((t & 1) == 0)
            g_s_part[bid][code] = __fadd_rn(sq, other);   // fixed order d0,d1
    }

    do_store(0);
    __syncthreads();
    do_ldg(1);

    // ---- pipelined main loop: one barrier per chunk ----
    for (int c = 0; c < NCHUNK; c++) {
        const float (*mm)[BMP]  = u.mb.m[c & 1];
        const float (*cc)[NCP2] = u.mb.c[c & 1];
        const int bcol = co * 8 + ((co >> 2) << 2);   // gap-padded B base col
        #pragma unroll
        for (int k = 0; k < BK; k++) {
            float4 a0 = *(const float4*)&mm[k][wo * 8];
            float4 a1 = *(const float4*)&mm[k][wo * 8 + 4];
            ulonglong2 q0 = *(const ulonglong2*)&cc[k][bcol];
            ulonglong2 q1 = *(const ulonglong2*)&cc[k][bcol + 4];
            const unsigned long long bp0 = q0.x, bp1 = q0.y, bp2 = q1.x, bp3 = q1.y;
            const float av[8] = {a0.x, a0.y, a0.z, a0.w, a1.x, a1.y, a1.z, a1.w};
            #pragma unroll
            for (int i = 0; i < 8; i++) {
                const unsigned long long aa = dup2(av[i]);
                ffma2(acc2[i][0], aa, bp0);
                ffma2(acc2[i][1], aa, bp1);
                ffma2(acc2[i][2], aa, bp2);
                ffma2(acc2[i][3], aa, bp3);
            }
        }
        if (c + 1 < NCHUNK) {
            do_store((c + 1) & 1);              // ascending chunk order -> chains intact
            if (c + 2 < NCHUNK) do_ldg(c + 2);
            __syncthreads();
        }
    }
    __syncthreads();   // all warps done reading tile buffers before epilogue overlay

    // ---- mnorm fold (LLVM order); u.eb.fold aliases the dead tile buffers ----
    u.eb.fold[lw][lq * 4 + 0] = macc0.x;
    u.eb.fold[lw][lq * 4 + 1] = macc0.y;
    u.eb.fold[lw][lq * 4 + 2] = macc0.z;
    u.eb.fold[lw][lq * 4 + 3] = macc0.w;
    u.eb.fold[64 + lw][lq * 4 + 0] = macc1.x;
    u.eb.fold[64 + lw][lq * 4 + 1] = macc1.y;
    u.eb.fold[64 + lw][lq * 4 + 2] = macc1.z;
    u.eb.fold[64 + lw][lq * 4 + 3] = macc1.w;
    __syncthreads();
    if (t < BM) {
        const float* s = u.eb.fold[t];
        float v0 = __fadd_rn(__fadd_rn(__fadd_rn(s[0], s[4]), s[8]),  s[12]);
        float v1 = __fadd_rn(__fadd_rn(__fadd_rn(s[1], s[5]), s[9]),  s[13]);
        float v2 = __fadd_rn(__fadd_rn(__fadd_rn(s[2], s[6]), s[10]), s[14]);
        float v3 = __fadd_rn(__fadd_rn(__fadd_rn(s[3], s[7]), s[11]), s[15]);
        sm_mn[t] = __fadd_rn(__fadd_rn(v0, v1), __fadd_rn(v2, v3));
    }
    __syncthreads();

    // ---- cnorm fold (fixed order; reuses fold cols 0..3) ----
    u.eb.fold[lw][lq]      = cnacc0;
    u.eb.fold[64 + lw][lq] = cnacc1;
    __syncthreads();
    if (t < NC) {
        const float* s = u.eb.fold[t];
        sm_cn[t] = __fadd_rn(__fadd_rn(__fadd_rn(s[0], s[1]), s[2]), s[3]);
    }
    __syncthreads();

    // ---- unpack + per-thread argmin, results to smem ----
    float cn[8];
    #pragma unroll
    for (int j = 0; j < 8; j++) cn[j] = sm_cn[co * 8 + j];

    #pragma unroll
    for (int i = 0; i < 8; i++) {
        float a[8];
        #pragma unroll
        for (int jp = 0; jp < 4; jp++) {
            float2 v = unpack2(acc2[i][jp]);
            a[2 * jp] = v.x; a[2 * jp + 1] = v.y;
        }
        const float mni = sm_mn[wo * 8 + i];
        float best;
        int bidx = co * 8;
        {
            float tt = __fadd_rn(mni, -a[0]);
            best = __fadd_rn(tt, cn[0]);
        }
        #pragma unroll
        for (int j = 1; j < 8; j++) {
            float tt = __fadd_rn(mni, -a[j]);
            float d2 = __fadd_rn(tt, cn[j]);
            if (d2 < best) { best = d2; bidx = co * 8 + j; }  // strict <: lowest j
        }
        u.eb.bs[wo * 8 + i][co] = best;
        u.eb.bi[wo * 8 + i][co] = bidx;
    }
    __syncthreads();

    // ---- per-word reduction over the 16 co-groups, ascending (first-min) ----
    if (t < BM) {
        float best = u.eb.bs[t][0];
        int   bidx = u.eb.bi[t][0];
        #pragma unroll
        for (int g = 1; g < 16; g++) {
            float s = u.eb.bs[t][g];
            if (s < best) { best = s; bidx = u.eb.bi[t][g]; } // strict <: lowest co
        }
        widx[t] = bidx;
        out_idx[wbase + t] = (float)bidx;
        atomicAdd(&hist[bidx], 1);
    }
    __syncthreads();

    if (t < NC) {
        int h = hist[t];
        if (h) atomicAdd(&g_count[t], h);
    }

    // ---- gather-write word_embeddings (codebook L2-hot, coalesced stores) ----
    for (int f = t; f < BM * (DIM / 4); f += 256) {
        const int wd = f >> 7;
        const int c4 = f & 127;
        const int c  = widx[wd];
        float4 v = *(const float4*)(cb + (size_t)c * DIM + c4 * 4);
        *(float4*)(out_emb + (size_t)(wbase + wd) * DIM + c4 * 4) = v;
    }

    // ---- last-CTA loss: sum_c count[c] * (sum_p s_part[p][c]) / (NWORDS*DIM) ----
    __syncthreads();
    if (t == 0) {
        __threadfence();
        unsigned old = atomicAdd(&g_done, 1u);
        is_last = (old == gridDim.x - 1) ? 1 : 0;
    }
    __syncthreads();
    if (is_last) {
        float v = 0.f;
        if (t < NC) {
            __threadfence();
            float s = 0.f;
            #pragma unroll 8
            for (int p = 0; p < GRID; p++)
                s = __fadd_rn(s, g_s_part[p][t]);   // fixed ascending order
            const int cnt = *(volatile int*)&g_count[t];
            v = __fmul_rn((float)cnt, s);
            g_count[t] = 0;                          // reset for next replay
        }
        #pragma unroll
        for (int o = 16; o; o >>= 1) v += __shfl_down_sync(0xffffffffu, v, o);
        if ((t & 31) == 0) sm_ls[t >> 5] = v;
        __syncthreads();
        if (t == 0) {
            float s = sm_ls[0];
            #pragma unroll
            for (int i = 1; i < 8; i++) s = __fadd_rn(s, sm_ls[i]);
            out_loss[0] = s * (1.0f / ((float)NWORDS * (float)DIM));
            g_done = 0;
        }
    }
}

// ---------------------------------------------------------------------------
// Inputs (metadata order):
//   d_in[0] char_tokens int32 (unused)  d_in[1] char_embeddings f32 [16,4096,512]
//   d_in[2] word_codebook f32 [128,512] d_in[3] proj_w f32 [512,512]
//   d_in[4] proj_b f32 [512]
// Output (f32, flattened): [0,32768) indices | [.., +32768*512) embeddings | [last] loss
// ---------------------------------------------------------------------------
extern "C" void kernel_launch(void* const* d_in, const int* in_sizes, int n_in,
                              void* d_out, int out_size) {
    const float* emb = (const float*)d_in[1];
    const float* cb  = (const float*)d_in[2];
    const float* W   = (const float*)d_in[3];
    const float* b   = (const float*)d_in[4];
    float* out = (float*)d_out;

    float* out_idx  = out;
    float* out_emb  = out + NWORDS;
    float* out_loss = out + NWORDS + (size_t)NWORDS * DIM;

    main_kernel<<<GRID, 256>>>(emb, cb, W, b, out_idx, out_emb, out_loss);
}

// round 11
// speedup vs baseline: 1.1495x; 1.1495x over previous
#include <cuda_runtime.h>
#include <cstdint>

// Problem constants (fixed by the reference: B=16, L=4096, D=512, WORD_SIZE=128, WORD_LEN=2)
#define NWORDS 32768     // B * (L/2)
#define DIM    512
#define NC     128       // codebook rows
#define BM     128       // words per CTA tile
#define BK     16        // k-chunk
#define BMP    (BM + 4)  // A smem pitch
#define NCP2   148       // B smem pitch: loads conflict-free, stores 2-way (16B-aligned rows)
#define NCHUNK (DIM / BK)
#define GRID   (NWORDS / BM)   // 256 CTAs
#define NDG    64              // d-groups for prep partials

// Scratch (no allocations allowed -> __device__ globals)
__device__ float    g_s_part[NDG][NC];   // partial ||P-C||^2 per (d-group, code)
__device__ int      g_count[NC];         // histogram of argmin indices
__device__ unsigned g_done;              // last-CTA election (zero-init; reset by last CTA)

// B smem column mapping: 4-float gap every 32 codes -> the 8 per-warp LDS.128
// load addresses land in distinct bank quads (conflict-free).
__device__ __forceinline__ int bcol_of(int c) { return c + ((c >> 5) << 2); }

// ---- packed f32x2 helpers (each half = independent IEEE fp32 op) -----------
__device__ __forceinline__ unsigned long long dup2(float x) {
    unsigned long long r;
    asm("mov.b64 %0, {%1, %1};" : "=l"(r) : "f"(x));
    return r;
}
__device__ __forceinline__ void ffma2(unsigned long long& d,
                                      unsigned long long a,
                                      unsigned long long b) {
    asm("fma.rn.f32x2 %0, %1, %2, %0;" : "+l"(d) : "l"(a), "l"(b));
}
__device__ __forceinline__ float2 unpack2(unsigned long long v) {
    float2 f;
    asm("mov.b64 {%0, %1}, %2;" : "=f"(f.x), "=f"(f.y) : "l"(v));
    return f;
}

// Overlay: GEMM tile buffers (main loop) vs epilogue arrays (after loop).
struct MainBufs {
    float m[2][BK][BMP];    // 16.9 KB
    float c[2][BK][NCP2];   // 18.9 KB
};
struct EpiBufs {
    float fold[BM][17];     // mnorm chains; cols 0..3 reused for cnorm
    float bs[BM][17];       // per-(word, co-group) best score
    int   bi[BM][17];       // and best index
};

// ---------------------------------------------------------------------------
// Single fused kernel:
//   coalesced prep-slice (32 codes x 8 d of ||C@W^T+b-C||^2)
//   -> pair-sum + mnorm(LLVM order) + cnorm
//   -> fp32 GEMM (f32x2, double-buffered, conflict-free B loads)
//   -> d2 rounding chain -> smem argmin -> histogram -> gather -> last-CTA loss.
//
// Bit-exactness invariants (rel_err==0.0 verified R7/R8, preserved):
//  * per-(word,code) dot: single fp32 accumulator, FMA over ascending k.
//  * mnorm: 16 chains part_p[l] = sum_i y[16i+4p+l] (ascending chunk i;
//    loader lq == p, component == l), fold ((P0+P1)+P2)+P3, (v0+v1)+(v2+v3).
//  * d2 = fl(fl(mnorm - acc) + cnorm); argmin first-min (lowest index).
//  * cnorm/loss: fixed fold order (loss-only precision, slack is huge).
// ---------------------------------------------------------------------------
__global__ __launch_bounds__(256, 2)
void main_kernel(const float* __restrict__ emb,   // [NWORDS*2, DIM]
                 const float* __restrict__ cb,    // [NC, DIM]
                 const float* __restrict__ W,     // [DIM, DIM]
                 const float* __restrict__ bias,  // [DIM]
                 float* __restrict__ out_idx,     // NWORDS floats
                 float* __restrict__ out_emb,     // NWORDS*DIM floats
                 float* __restrict__ out_loss) {  // 1 float
    __shared__ __align__(16) union { MainBufs mb; EpiBufs eb; } u;   // ~35.8 KB
    __shared__ float sm_mn[BM];
    __shared__ float sm_cn[NC];
    __shared__ float sm_ls[8];
    __shared__ int   widx[BM];
    __shared__ int   hist[NC];
    __shared__ int   is_last;

    const int t = threadIdx.x;
    const int bid = blockIdx.x;
    const int wbase = bid * BM;

    if (t < NC) hist[t] = 0;

    // compute-map: warp tile = 32 words x 64 codes (4 wq x 8 cq)
    const int w  = t >> 5, l = t & 31;
    const int wo = ((w >> 1) << 2) + (l >> 3);   // 0..15 word group (8 words)
    const int co = ((w & 1) << 3) + (l & 7);     // 0..15 code group (8 codes)
    // loader-map (fixed: mnorm chain identity depends on it)
    const int lw = t >> 2;   // 0..63
    const int lq = t & 3;    // 0..3  (== mnorm part index p)

    unsigned long long acc2[8][4];
    #pragma unroll
    for (int i = 0; i < 8; i++)
        #pragma unroll
        for (int jp = 0; jp < 4; jp++) acc2[i][jp] = 0ull;

    float4 macc0 = make_float4(0.f, 0.f, 0.f, 0.f);
    float4 macc1 = make_float4(0.f, 0.f, 0.f, 0.f);
    float  cnacc0 = 0.f, cnacc1 = 0.f;

    float4 pa00, pa01, pa10, pa11, pb0, pb1;

    auto do_ldg = [&](int c) {
        const int kc = c * BK;
        const size_t r0 = (size_t)(wbase + lw) * 2 * DIM + kc + lq * 4;
        const size_t r1 = r0 + (size_t)64 * 2 * DIM;
        pa00 = *(const float4*)(emb + r0);
        pa01 = *(const float4*)(emb + r0 + DIM);
        pa10 = *(const float4*)(emb + r1);
        pa11 = *(const float4*)(emb + r1 + DIM);
        pb0  = *(const float4*)(cb + (size_t)lw * DIM + kc + lq * 4);
        pb1  = *(const float4*)(cb + (size_t)(64 + lw) * DIM + kc + lq * 4);
    };

    const int bc0 = bcol_of(lw);        // B smem column for code lw
    const int bc1 = bcol_of(64 + lw);   // and code 64+lw

    auto do_store = [&](int buf) {
        float (*mm)[BMP]  = u.mb.m[buf];
        float (*cc)[NCP2] = u.mb.c[buf];
        float s0 = __fadd_rn(pa00.x, pa01.x);
        float s1 = __fadd_rn(pa00.y, pa01.y);
        float s2 = __fadd_rn(pa00.z, pa01.z);
        float s3 = __fadd_rn(pa00.w, pa01.w);
        mm[lq * 4 + 0][lw] = s0;
        mm[lq * 4 + 1][lw] = s1;
        mm[lq * 4 + 2][lw] = s2;
        mm[lq * 4 + 3][lw] = s3;
        float m0 = __fmul_rn(s0, 0.5f), m1 = __fmul_rn(s1, 0.5f);
        float m2 = __fmul_rn(s2, 0.5f), m3 = __fmul_rn(s3, 0.5f);
        macc0.x = __fadd_rn(macc0.x, __fmul_rn(m0, m0));
        macc0.y = __fadd_rn(macc0.y, __fmul_rn(m1, m1));
        macc0.z = __fadd_rn(macc0.z, __fmul_rn(m2, m2));
        macc0.w = __fadd_rn(macc0.w, __fmul_rn(m3, m3));

        s0 = __fadd_rn(pa10.x, pa11.x);
        s1 = __fadd_rn(pa10.y, pa11.y);
        s2 = __fadd_rn(pa10.z, pa11.z);
        s3 = __fadd_rn(pa10.w, pa11.w);
        mm[lq * 4 + 0][64 + lw] = s0;
        mm[lq * 4 + 1][64 + lw] = s1;
        mm[lq * 4 + 2][64 + lw] = s2;
        mm[lq * 4 + 3][64 + lw] = s3;
        m0 = __fmul_rn(s0, 0.5f); m1 = __fmul_rn(s1, 0.5f);
        m2 = __fmul_rn(s2, 0.5f); m3 = __fmul_rn(s3, 0.5f);
        macc1.x = __fadd_rn(macc1.x, __fmul_rn(m0, m0));
        macc1.y = __fadd_rn(macc1.y, __fmul_rn(m1, m1));
        macc1.z = __fadd_rn(macc1.z, __fmul_rn(m2, m2));
        macc1.w = __fadd_rn(macc1.w, __fmul_rn(m3, m3));

        cc[lq * 4 + 0][bc0] = pb0.x;
        cc[lq * 4 + 1][bc0] = pb0.y;
        cc[lq * 4 + 2][bc0] = pb0.z;
        cc[lq * 4 + 3][bc0] = pb0.w;
        cc[lq * 4 + 0][bc1] = pb1.x;
        cc[lq * 4 + 1][bc1] = pb1.y;
        cc[lq * 4 + 2][bc1] = pb1.z;
        cc[lq * 4 + 3][bc1] = pb1.w;
        cnacc0 = __fmaf_rn(pb0.x, pb0.x, cnacc0);
        cnacc0 = __fmaf_rn(pb0.y, pb0.y, cnacc0);
        cnacc0 = __fmaf_rn(pb0.z, pb0.z, cnacc0);
        cnacc0 = __fmaf_rn(pb0.w, pb0.w, cnacc0);
        cnacc1 = __fmaf_rn(pb1.x, pb1.x, cnacc1);
        cnacc1 = __fmaf_rn(pb1.y, pb1.y, cnacc1);
        cnacc1 = __fmaf_rn(pb1.z, pb1.z, cnacc1);
        cnacc1 = __fmaf_rn(pb1.w, pb1.w, cnacc1);
    };

    // ---- issue chunk-0 loads, then overlap the prep slice under their latency
    do_ldg(0);

    // ---- prep slice (COALESCED): CTA (cg = bid&3, dg = bid>>2) computes
    //      partial s over d in [dg*8, dg*8+8) for codes [cg*32, cg*32+32).
    //      Warp wp owns 4 codes; lanes split k (stride-32, 128B-coalesced).
    //      Loss-only -> any dot order; per-code dd-fold fixed ascending.
    {
        const int cg = bid & 3, dg = bid >> 2;
        const int wp = w, ln = l;
        #pragma unroll
        for (int ci = 0; ci < 4; ci++) {
            const int c = cg * 32 + wp * 4 + ci;
            const float* crow = cb + (size_t)c * DIM;
            float creg[16];
            #pragma unroll
            for (int j = 0; j < 16; j++) creg[j] = __ldg(&crow[ln + 32 * j]);
            float ssum = 0.f;
            #pragma unroll
            for (int dd = 0; dd < 8; dd++) {
                const int d = dg * 8 + dd;
                const float* wrow = W + (size_t)d * DIM;
                float p = 0.f;
                #pragma unroll
                for (int j = 0; j < 16; j++)
                    p = __fmaf_rn(creg[j], __ldg(&wrow[ln + 32 * j]), p);
                #pragma unroll
                for (int o = 16; o; o >>= 1)
                    p += __shfl_down_sync(0xffffffffu, p, o);
                if (ln == 0) {
                    float diff = p + __ldg(&bias[d]) - __ldg(&crow[d]);
                    ssum = __fadd_rn(ssum, diff * diff);
                }
            }
            if (ln == 0) g_s_part[dg][c] = ssum;
        }
    }

    do_store(0);
    __syncthreads();
    do_ldg(1);

    // ---- pipelined main loop: one barrier per chunk ----
    for (int c = 0; c < NCHUNK; c++) {
        const float (*mm)[BMP]  = u.mb.m[c & 1];
        const float (*cc)[NCP2] = u.mb.c[c & 1];
        const int bcol = co * 8 + ((co >> 2) << 2);   // gap-padded B base col
        #pragma unroll
        for (int k = 0; k < BK; k++) {
            float4 a0 = *(const float4*)&mm[k][wo * 8];
            float4 a1 = *(const float4*)&mm[k][wo * 8 + 4];
            ulonglong2 q0 = *(const ulonglong2*)&cc[k][bcol];
            ulonglong2 q1 = *(const ulonglong2*)&cc[k][bcol + 4];
            const unsigned long long bp0 = q0.x, bp1 = q0.y, bp2 = q1.x, bp3 = q1.y;
            const float av[8] = {a0.x, a0.y, a0.z, a0.w, a1.x, a1.y, a1.z, a1.w};
            #pragma unroll
            for (int i = 0; i < 8; i++) {
                const unsigned long long aa = dup2(av[i]);
                ffma2(acc2[i][0], aa, bp0);
                ffma2(acc2[i][1], aa, bp1);
                ffma2(acc2[i][2], aa, bp2);
                ffma2(acc2[i][3], aa, bp3);
            }
        }
        if (c + 1 < NCHUNK) {
            do_store((c + 1) & 1);              // ascending chunk order -> chains intact
            if (c + 2 < NCHUNK) do_ldg(c + 2);
            __syncthreads();
        }
    }
    __syncthreads();   // all warps done reading tile buffers before epilogue overlay

    // ---- mnorm fold (LLVM order); u.eb.fold aliases the dead tile buffers ----
    u.eb.fold[lw][lq * 4 + 0] = macc0.x;
    u.eb.fold[lw][lq * 4 + 1] = macc0.y;
    u.eb.fold[lw][lq * 4 + 2] = macc0.z;
    u.eb.fold[lw][lq * 4 + 3] = macc0.w;
    u.eb.fold[64 + lw][lq * 4 + 0] = macc1.x;
    u.eb.fold[64 + lw][lq * 4 + 1] = macc1.y;
    u.eb.fold[64 + lw][lq * 4 + 2] = macc1.z;
    u.eb.fold[64 + lw][lq * 4 + 3] = macc1.w;
    __syncthreads();
    if (t < BM) {
        const float* s = u.eb.fold[t];
        float v0 = __fadd_rn(__fadd_rn(__fadd_rn(s[0], s[4]), s[8]),  s[12]);
        float v1 = __fadd_rn(__fadd_rn(__fadd_rn(s[1], s[5]), s[9]),  s[13]);
        float v2 = __fadd_rn(__fadd_rn(__fadd_rn(s[2], s[6]), s[10]), s[14]);
        float v3 = __fadd_rn(__fadd_rn(__fadd_rn(s[3], s[7]), s[11]), s[15]);
        sm_mn[t] = __fadd_rn(__fadd_rn(v0, v1), __fadd_rn(v2, v3));
    }
    __syncthreads();

    // ---- cnorm fold (fixed order; reuses fold cols 0..3) ----
    u.eb.fold[lw][lq]      = cnacc0;
    u.eb.fold[64 + lw][lq] = cnacc1;
    __syncthreads();
    if (t < NC) {
        const float* s = u.eb.fold[t];
        sm_cn[t] = __fadd_rn(__fadd_rn(__fadd_rn(s[0], s[1]), s[2]), s[3]);
    }
    __syncthreads();

    // ---- unpack + per-thread argmin, results to smem ----
    float cn[8];
    #pragma unroll
    for (int j = 0; j < 8; j++) cn[j] = sm_cn[co * 8 + j];

    #pragma unroll
    for (int i = 0; i < 8; i++) {
        float a[8];
        #pragma unroll
        for (int jp = 0; jp < 4; jp++) {
            float2 v = unpack2(acc2[i][jp]);
            a[2 * jp] = v.x; a[2 * jp + 1] = v.y;
        }
        const float mni = sm_mn[wo * 8 + i];
        float best;
        int bidx = co * 8;
        {
            float tt = __fadd_rn(mni, -a[0]);
            best = __fadd_rn(tt, cn[0]);
        }
        #pragma unroll
        for (int j = 1; j < 8; j++) {
            float tt = __fadd_rn(mni, -a[j]);
            float d2 = __fadd_rn(tt, cn[j]);
            if (d2 < best) { best = d2; bidx = co * 8 + j; }  // strict <: lowest j
        }
        u.eb.bs[wo * 8 + i][co] = best;
        u.eb.bi[wo * 8 + i][co] = bidx;
    }
    __syncthreads();

    // ---- per-word reduction over the 16 co-groups, ascending (first-min) ----
    if (t < BM) {
        float best = u.eb.bs[t][0];
        int   bidx = u.eb.bi[t][0];
        #pragma unroll
        for (int g = 1; g < 16; g++) {
            float s = u.eb.bs[t][g];
            if (s < best) { best = s; bidx = u.eb.bi[t][g]; } // strict <: lowest co
        }
        widx[t] = bidx;
        out_idx[wbase + t] = (float)bidx;
        atomicAdd(&hist[bidx], 1);
    }
    __syncthreads();

    if (t < NC) {
        int h = hist[t];
        if (h) atomicAdd(&g_count[t], h);
    }

    // ---- gather-write word_embeddings (codebook L2-hot, coalesced stores) ----
    for (int f = t; f < BM * (DIM / 4); f += 256) {
        const int wd = f >> 7;
        const int c4 = f & 127;
        const int c  = widx[wd];
        float4 v = *(const float4*)(cb + (size_t)c * DIM + c4 * 4);
        *(float4*)(out_emb + (size_t)(wbase + wd) * DIM + c4 * 4) = v;
    }

    // ---- last-CTA loss: sum_c count[c] * (sum_dg s_part[dg][c]) / (NWORDS*DIM) ----
    __syncthreads();
    if (t == 0) {
        __threadfence();
        unsigned old = atomicAdd(&g_done, 1u);
        is_last = (old == gridDim.x - 1) ? 1 : 0;
    }
    __syncthreads();
    if (is_last) {
        float v = 0.f;
        if (t < NC) {
            __threadfence();
            float s = 0.f;
            #pragma unroll 8
            for (int p = 0; p < NDG; p++)
                s = __fadd_rn(s, g_s_part[p][t]);   // fixed ascending order
            const int cnt = *(volatile int*)&g_count[t];
            v = __fmul_rn((float)cnt, s);
            g_count[t] = 0;                          // reset for next replay
        }
        #pragma unroll
        for (int o = 16; o; o >>= 1) v += __shfl_down_sync(0xffffffffu, v, o);
        if ((t & 31) == 0) sm_ls[t >> 5] = v;
        __syncthreads();
        if (t == 0) {
            float s = sm_ls[0];
            #pragma unroll
            for (int i = 1; i < 8; i++) s = __fadd_rn(s, sm_ls[i]);
            out_loss[0] = s * (1.0f / ((float)NWORDS * (float)DIM));
            g_done = 0;
        }
    }
}

// ---------------------------------------------------------------------------
// Inputs (metadata order):
//   d_in[0] char_tokens int32 (unused)  d_in[1] char_embeddings f32 [16,4096,512]
//   d_in[2] word_codebook f32 [128,512] d_in[3] proj_w f32 [512,512]
//   d_in[4] proj_b f32 [512]
// Output (f32, flattened): [0,32768) indices | [.., +32768*512) embeddings | [last] loss
// ---------------------------------------------------------------------------
extern "C" void kernel_launch(void* const* d_in, const int* in_sizes, int n_in,
                              void* d_out, int out_size) {
    const float* emb = (const float*)d_in[1];
    const float* cb  = (const float*)d_in[2];
    const float* W   = (const float*)d_in[3];
    const float* b   = (const float*)d_in[4];
    float* out = (float*)d_out;

    float* out_idx  = out;
    float* out_emb  = out + NWORDS;
    float* out_loss = out + NWORDS + (size_t)NWORDS * DIM;

    main_kernel<<<GRID, 256>>>(emb, cb, W, b, out_idx, out_emb, out_loss);
}

// round 12
// speedup vs baseline: 1.2998x; 1.1308x over previous
#include <cuda_runtime.h>
#include <cstdint>

// Problem constants (fixed by the reference: B=16, L=4096, D=512, WORD_SIZE=128, WORD_LEN=2)
#define NWORDS 32768     // B * (L/2)
#define DIM    512
#define NC     128       // codebook rows
#define BM     128       // words per CTA tile
#define BK     16        // k-chunk
#define BMP    (BM + 4)  // A smem pitch (2-way STS conflict, conflict-free loads)
#define NCP2   148       // B smem pitch: gap-padded, conflict-free LDS.128 loads
#define NCHUNK (DIM / BK)
#define GRID   (NWORDS / BM)   // 256 CTAs
#define NDG    64              // d-groups for prep partials

// Scratch (no allocations allowed -> __device__ globals)
__device__ float    g_cbT[DIM * NC];     // transposed codebook: cbT[k][c]
__device__ float    g_cnorm[NC];         // ||C_c||^2 (fixed-order, R6-validated path)
__device__ float    g_s_part[NDG][NC];   // partial ||P-C||^2 per (d-group, code)
__device__ int      g_count[NC];         // histogram of argmin indices
__device__ unsigned g_done;              // last-CTA election (zero-init; reset by last CTA)

// B smem column mapping: 4-float gap every 32 codes -> per-warp LDS.128 load
// addresses land in distinct bank quads (conflict-free).
__device__ __forceinline__ int bcol_of(int c) { return c + ((c >> 5) << 2); }

// ---- packed f32x2 helpers (each half = independent IEEE fp32 op) -----------
__device__ __forceinline__ unsigned long long dup2(float x) {
    unsigned long long r;
    asm("mov.b64 %0, {%1, %1};" : "=l"(r) : "f"(x));
    return r;
}
__device__ __forceinline__ void ffma2(unsigned long long& d,
                                      unsigned long long a,
                                      unsigned long long b) {
    asm("fma.rn.f32x2 %0, %1, %2, %0;" : "+l"(d) : "l"(a), "l"(b));
}
__device__ __forceinline__ float2 unpack2(unsigned long long v) {
    float2 f;
    asm("mov.b64 {%0, %1}, %2;" : "=f"(f.x), "=f"(f.y) : "l"(v));
    return f;
}

// Overlay: GEMM tile buffers (main loop) vs epilogue arrays (after loop).
struct MainBufs {
    float m[2][BK][BMP];    // 16.9 KB
    float c[2][BK][NCP2];   // 18.9 KB
};
struct EpiBufs {
    float fold[BM][17];     // mnorm chains
    float bs[BM][17];       // per-(word, co-group) best score
    int   bi[BM][17];       // and best index
};

// ---------------------------------------------------------------------------
// Kernel 0: transpose codebook (cbT[k][c] = cb[c][k]) + cnorm[c] (fixed-order
// fold, same deterministic-global-cnorm class that passed with rel_err==0.0
// in R6/R7). 128 blocks x 256 threads, ~4 us.
// ---------------------------------------------------------------------------
__global__ __launch_bounds__(256)
void transpose_kernel(const float* __restrict__ cb) {
    const int c = blockIdx.x;      // code row
    const int t = threadIdx.x;     // 256
    __shared__ float wsum[8];

    const float v0 = __ldg(&cb[(size_t)c * DIM + t]);
    const float v1 = __ldg(&cb[(size_t)c * DIM + t + 256]);
    g_cbT[(size_t)t * NC + c]         = v0;
    g_cbT[(size_t)(t + 256) * NC + c] = v1;

    float n = __fmaf_rn(v0, v0, __fmul_rn(v1, v1));
    #pragma unroll
    for (int o = 16; o; o >>= 1) n += __shfl_down_sync(0xffffffffu, n, o);
    if ((t & 31) == 0) wsum[t >> 5] = n;
    __syncthreads();
    if (t == 0) {
        float s = wsum[0];
        #pragma unroll
        for (int i = 1; i < 8; i++) s = __fadd_rn(s, wsum[i]);
        g_cnorm[c] = s;
    }
}

// ---------------------------------------------------------------------------
// Kernel 1: fused  coalesced prep-slice -> pair-sum + mnorm(LLVM order)
//   -> fp32 GEMM (f32x2, double-buffered; A via LDG+STS, B via cp.async from
//      cbT; store/ldg issued BEFORE compute so the barrier never drains STS)
//   -> d2 rounding chain -> smem argmin -> histogram -> gather -> last-CTA loss.
//
// Bit-exactness invariants (rel_err==0.0 verified R7/R8, preserved):
//  * per-(word,code) dot: single fp32 accumulator, FMA over ascending k.
//  * mnorm: 16 chains part_p[l] = sum_i y[16i+4p+l] (ascending chunk i;
//    loader lq == p, component == l), fold ((P0+P1)+P2)+P3, (v0+v1)+(v2+v3).
//  * d2 = fl(fl(mnorm - acc) + cnorm); argmin first-min (lowest index).
//  * cnorm/loss: fixed fold order (order noise ~1e-9 << 3e-5 d2 granularity).
// ---------------------------------------------------------------------------
__global__ __launch_bounds__(256, 2)
void main_kernel(const float* __restrict__ emb,   // [NWORDS*2, DIM]
                 const float* __restrict__ cb,    // [NC, DIM]
                 const float* __restrict__ W,     // [DIM, DIM]
                 const float* __restrict__ bias,  // [DIM]
                 float* __restrict__ out_idx,     // NWORDS floats
                 float* __restrict__ out_emb,     // NWORDS*DIM floats
                 float* __restrict__ out_loss) {  // 1 float
    __shared__ __align__(16) union { MainBufs mb; EpiBufs eb; } u;   // 35.8 KB
    __shared__ float sm_mn[BM];
    __shared__ float sm_ls[8];
    __shared__ int   widx[BM];
    __shared__ int   hist[NC];
    __shared__ int   is_last;

    const int t = threadIdx.x;
    const int bid = blockIdx.x;
    const int wbase = bid * BM;

    if (t < NC) hist[t] = 0;

    // compute-map: warp tile = 32 words x 64 codes (4 wq x 8 cq)
    const int w  = t >> 5, l = t & 31;
    const int wo = ((w >> 1) << 2) + (l >> 3);   // 0..15 word group (8 words)
    const int co = ((w & 1) << 3) + (l & 7);     // 0..15 code group (8 codes)
    // loader-map (fixed: mnorm chain identity depends on it)
    const int lw = t >> 2;   // 0..63
    const int lq = t & 3;    // 0..3  (== mnorm part index p)

    unsigned long long acc2[8][4];
    #pragma unroll
    for (int i = 0; i < 8; i++)
        #pragma unroll
        for (int jp = 0; jp < 4; jp++) acc2[i][jp] = 0ull;

    float4 macc0 = make_float4(0.f, 0.f, 0.f, 0.f);
    float4 macc1 = make_float4(0.f, 0.f, 0.f, 0.f);

    float4 pa00, pa01, pa10, pa11;   // A register prefetch

    auto do_ldg = [&](int c) {
        const int kc = c * BK;
        const size_t r0 = (size_t)(wbase + lw) * 2 * DIM + kc + lq * 4;
        const size_t r1 = r0 + (size_t)64 * 2 * DIM;
        pa00 = *(const float4*)(emb + r0);
        pa01 = *(const float4*)(emb + r0 + DIM);
        pa10 = *(const float4*)(emb + r1);
        pa11 = *(const float4*)(emb + r1 + DIM);
    };

    auto do_store = [&](int buf) {
        float (*mm)[BMP] = u.mb.m[buf];
        float s0 = __fadd_rn(pa00.x, pa01.x);
        float s1 = __fadd_rn(pa00.y, pa01.y);
        float s2 = __fadd_rn(pa00.z, pa01.z);
        float s3 = __fadd_rn(pa00.w, pa01.w);
        mm[lq * 4 + 0][lw] = s0;
        mm[lq * 4 + 1][lw] = s1;
        mm[lq * 4 + 2][lw] = s2;
        mm[lq * 4 + 3][lw] = s3;
        float m0 = __fmul_rn(s0, 0.5f), m1 = __fmul_rn(s1, 0.5f);
        float m2 = __fmul_rn(s2, 0.5f), m3 = __fmul_rn(s3, 0.5f);
        macc0.x = __fadd_rn(macc0.x, __fmul_rn(m0, m0));
        macc0.y = __fadd_rn(macc0.y, __fmul_rn(m1, m1));
        macc0.z = __fadd_rn(macc0.z, __fmul_rn(m2, m2));
        macc0.w = __fadd_rn(macc0.w, __fmul_rn(m3, m3));

        s0 = __fadd_rn(pa10.x, pa11.x);
        s1 = __fadd_rn(pa10.y, pa11.y);
        s2 = __fadd_rn(pa10.z, pa11.z);
        s3 = __fadd_rn(pa10.w, pa11.w);
        mm[lq * 4 + 0][64 + lw] = s0;
        mm[lq * 4 + 1][64 + lw] = s1;
        mm[lq * 4 + 2][64 + lw] = s2;
        mm[lq * 4 + 3][64 + lw] = s3;
        m0 = __fmul_rn(s0, 0.5f); m1 = __fmul_rn(s1, 0.5f);
        m2 = __fmul_rn(s2, 0.5f); m3 = __fmul_rn(s3, 0.5f);
        macc1.x = __fadd_rn(macc1.x, __fmul_rn(m0, m0));
        macc1.y = __fadd_rn(macc1.y, __fmul_rn(m1, m1));
        macc1.z = __fadd_rn(macc1.z, __fmul_rn(m2, m2));
        macc1.w = __fadd_rn(macc1.w, __fmul_rn(m3, m3));
    };

    // B-tile prefetch via cp.async: chunk c = cbT rows [16c, 16c+16), each row
    // 128 contiguous floats -> 2x 16B copies per thread into gap-padded smem.
    auto cp_b = [&](int c) {
        #pragma unroll
        for (int qq = 0; qq < 2; qq++) {
            const int q   = t * 2 + qq;      // 0..511
            const int row = q >> 5;          // k within chunk
            const int grp = q & 31;          // 4-code group (never crosses 32-boundary)
            const float* src = g_cbT + (size_t)(c * BK + row) * NC + grp * 4;
            uint32_t dst = (uint32_t)__cvta_generic_to_shared(
                &u.mb.c[c & 1][row][grp * 4 + ((grp >> 3) << 2)]);
            asm volatile("cp.async.cg.shared.global [%0], [%1], 16;"
                         :: "r"(dst), "l"(src));
        }
        asm volatile("cp.async.commit_group;" ::: "memory");
    };

    // ---- prologue: A0 + B0 in flight, prep slice overlapped under latency ----
    do_ldg(0);
    cp_b(0);

    // prep slice (COALESCED): CTA (cg = bid&3, dg = bid>>2) computes partial s
    // over d in [dg*8, dg*8+8) for codes [cg*32, cg*32+32).  Loss-only.
    {
        const int cg = bid & 3, dg = bid >> 2;
        const int wp = w, ln = l;
        #pragma unroll
        for (int ci = 0; ci < 4; ci++) {
            const int c = cg * 32 + wp * 4 + ci;
            const float* crow = cb + (size_t)c * DIM;
            float creg[16];
            #pragma unroll
            for (int j = 0; j < 16; j++) creg[j] = __ldg(&crow[ln + 32 * j]);
            float ssum = 0.f;
            #pragma unroll
            for (int dd = 0; dd < 8; dd++) {
                const int d = dg * 8 + dd;
                const float* wrow = W + (size_t)d * DIM;
                float p = 0.f;
                #pragma unroll
                for (int j = 0; j < 16; j++)
                    p = __fmaf_rn(creg[j], __ldg(&wrow[ln + 32 * j]), p);
                #pragma unroll
                for (int o = 16; o; o >>= 1)
                    p += __shfl_down_sync(0xffffffffu, p, o);
                if (ln == 0) {
                    float diff = p + __ldg(&bias[d]) - __ldg(&crow[d]);
                    ssum = __fadd_rn(ssum, diff * diff);
                }
            }
            if (ln == 0) g_s_part[dg][c] = ssum;
        }
    }

    do_store(0);
    do_ldg(1);
    asm volatile("cp.async.wait_group 0;" ::: "memory");
    __syncthreads();

    // ---- pipelined main loop: store/prefetch FIRST, then compute, then bar.
    //      STS/LDGSTS have a full compute chunk to drain -> cheap barrier. ----
    for (int c = 0; c < NCHUNK; c++) {
        if (c + 1 < NCHUNK) {
            do_store((c + 1) & 1);   // ascending chunk order -> mnorm chains intact
            cp_b(c + 1);
        }
        if (c + 2 < NCHUNK) do_ldg(c + 2);

        const float (*mm)[BMP]  = u.mb.m[c & 1];
        const float (*cc)[NCP2] = u.mb.c[c & 1];
        const int bcol = co * 8 + ((co >> 2) << 2);   // gap-padded B base col
        #pragma unroll
        for (int k = 0; k < BK; k++) {
            float4 a0 = *(const float4*)&mm[k][wo * 8];
            float4 a1 = *(const float4*)&mm[k][wo * 8 + 4];
            ulonglong2 q0 = *(const ulonglong2*)&cc[k][bcol];
            ulonglong2 q1 = *(const ulonglong2*)&cc[k][bcol + 4];
            const unsigned long long bp0 = q0.x, bp1 = q0.y, bp2 = q1.x, bp3 = q1.y;
            const float av[8] = {a0.x, a0.y, a0.z, a0.w, a1.x, a1.y, a1.z, a1.w};
            #pragma unroll
            for (int i = 0; i < 8; i++) {
                const unsigned long long aa = dup2(av[i]);
                ffma2(acc2[i][0], aa, bp0);
                ffma2(acc2[i][1], aa, bp1);
                ffma2(acc2[i][2], aa, bp2);
                ffma2(acc2[i][3], aa, bp3);
            }
        }
        if (c + 1 < NCHUNK) {
            asm volatile("cp.async.wait_group 0;" ::: "memory");
            __syncthreads();
        }
    }
    __syncthreads();   // all warps done reading tile buffers before epilogue overlay

    // ---- mnorm fold (LLVM order); u.eb.fold aliases the dead tile buffers ----
    u.eb.fold[lw][lq * 4 + 0] = macc0.x;
    u.eb.fold[lw][lq * 4 + 1] = macc0.y;
    u.eb.fold[lw][lq * 4 + 2] = macc0.z;
    u.eb.fold[lw][lq * 4 + 3] = macc0.w;
    u.eb.fold[64 + lw][lq * 4 + 0] = macc1.x;
    u.eb.fold[64 + lw][lq * 4 + 1] = macc1.y;
    u.eb.fold[64 + lw][lq * 4 + 2] = macc1.z;
    u.eb.fold[64 + lw][lq * 4 + 3] = macc1.w;
    __syncthreads();
    if (t < BM) {
        const float* s = u.eb.fold[t];
        float v0 = __fadd_rn(__fadd_rn(__fadd_rn(s[0], s[4]), s[8]),  s[12]);
        float v1 = __fadd_rn(__fadd_rn(__fadd_rn(s[1], s[5]), s[9]),  s[13]);
        float v2 = __fadd_rn(__fadd_rn(__fadd_rn(s[2], s[6]), s[10]), s[14]);
        float v3 = __fadd_rn(__fadd_rn(__fadd_rn(s[3], s[7]), s[11]), s[15]);
        sm_mn[t] = __fadd_rn(__fadd_rn(v0, v1), __fadd_rn(v2, v3));
    }
    __syncthreads();

    // ---- unpack + per-thread argmin, results to smem ----
    float cn[8];
    #pragma unroll
    for (int j = 0; j < 8; j++) cn[j] = __ldg(&g_cnorm[co * 8 + j]);

    #pragma unroll
    for (int i = 0; i < 8; i++) {
        float a[8];
        #pragma unroll
        for (int jp = 0; jp < 4; jp++) {
            float2 v = unpack2(acc2[i][jp]);
            a[2 * jp] = v.x; a[2 * jp + 1] = v.y;
        }
        const float mni = sm_mn[wo * 8 + i];
        float best;
        int bidx = co * 8;
        {
            float tt = __fadd_rn(mni, -a[0]);
            best = __fadd_rn(tt, cn[0]);
        }
        #pragma unroll
        for (int j = 1; j < 8; j++) {
            float tt = __fadd_rn(mni, -a[j]);
            float d2 = __fadd_rn(tt, cn[j]);
            if (d2 < best) { best = d2; bidx = co * 8 + j; }  // strict <: lowest j
        }
        u.eb.bs[wo * 8 + i][co] = best;
        u.eb.bi[wo * 8 + i][co] = bidx;
    }
    __syncthreads();

    // ---- per-word reduction over the 16 co-groups, ascending (first-min) ----
    if (t < BM) {
        float best = u.eb.bs[t][0];
        int   bidx = u.eb.bi[t][0];
        #pragma unroll
        for (int g = 1; g < 16; g++) {
            float s = u.eb.bs[t][g];
            if (s < best) { best = s; bidx = u.eb.bi[t][g]; } // strict <: lowest co
        }
        widx[t] = bidx;
        out_idx[wbase + t] = (float)bidx;
        atomicAdd(&hist[bidx], 1);
    }
    __syncthreads();

    if (t < NC) {
        int h = hist[t];
        if (h) atomicAdd(&g_count[t], h);
    }

    // ---- gather-write word_embeddings (codebook L2-hot, coalesced stores) ----
    for (int f = t; f < BM * (DIM / 4); f += 256) {
        const int wd = f >> 7;
        const int c4 = f & 127;
        const int c  = widx[wd];
        float4 v = *(const float4*)(cb + (size_t)c * DIM + c4 * 4);
        *(float4*)(out_emb + (size_t)(wbase + wd) * DIM + c4 * 4) = v;
    }

    // ---- last-CTA loss: sum_c count[c] * (sum_dg s_part[dg][c]) / (NWORDS*DIM) ----
    __syncthreads();
    if (t == 0) {
        __threadfence();
        unsigned old = atomicAdd(&g_done, 1u);
        is_last = (old == gridDim.x - 1) ? 1 : 0;
    }
    __syncthreads();
    if (is_last) {
        float v = 0.f;
        if (t < NC) {
            __threadfence();
            float s = 0.f;
            #pragma unroll 8
            for (int p = 0; p < NDG; p++)
                s = __fadd_rn(s, g_s_part[p][t]);   // fixed ascending order
            const int cnt = *(volatile int*)&g_count[t];
            v = __fmul_rn((float)cnt, s);
            g_count[t] = 0;                          // reset for next replay
        }
        #pragma unroll
        for (int o = 16; o; o >>= 1) v += __shfl_down_sync(0xffffffffu, v, o);
        if ((t & 31) == 0) sm_ls[t >> 5] = v;
        __syncthreads();
        if (t == 0) {
            float s = sm_ls[0];
            #pragma unroll
            for (int i = 1; i < 8; i++) s = __fadd_rn(s, sm_ls[i]);
            out_loss[0] = s * (1.0f / ((float)NWORDS * (float)DIM));
            g_done = 0;
        }
    }
}

// ---------------------------------------------------------------------------
// Inputs (metadata order):
//   d_in[0] char_tokens int32 (unused)  d_in[1] char_embeddings f32 [16,4096,512]
//   d_in[2] word_codebook f32 [128,512] d_in[3] proj_w f32 [512,512]
//   d_in[4] proj_b f32 [512]
// Output (f32, flattened): [0,32768) indices | [.., +32768*512) embeddings | [last] loss
// ---------------------------------------------------------------------------
extern "C" void kernel_launch(void* const* d_in, const int* in_sizes, int n_in,
                              void* d_out, int out_size) {
    const float* emb = (const float*)d_in[1];
    const float* cb  = (const float*)d_in[2];
    const float* W   = (const float*)d_in[3];
    const float* b   = (const float*)d_in[4];
    float* out = (float*)d_out;

    float* out_idx  = out;
    float* out_emb  = out + NWORDS;
    float* out_loss = out + NWORDS + (size_t)NWORDS * DIM;

    transpose_kernel<<<NC, 256>>>(cb);
    main_kernel<<<GRID, 256>>>(emb, cb, W, b, out_idx, out_emb, out_loss);
}